// round 15
// baseline (speedup 1.0000x reference)
#include <cuda_runtime.h>
#include <cuda_fp16.h>
#include <cstdint>

#define EXP    8
#define DIN    2048
#define DOUT   2048
#define NTOK   4096
#define KROUTE 2
#define MTOT   (NTOK * KROUTE)

#define TM 128
#define TN 256
#define TK 64
#define KB (DIN / TK)             // 32
#define NSTG 3
#define LDSS 72                   // padded smem row stride in fp16 elems (144B)
#define ATILE (TM * LDSS * 2)     // 18432 B
#define WTILE (TN * LDSS * 2)     // 36864 B
#define STGB  (ATILE + WTILE)     // 55296 B per stage

#define WEFF_BLOCKS (EXP * 32 * 32)          // 8192
#define PREPX_BLOCKS ((NTOK * DIN) / 1024)   // 8192

// ---- scratch (device globals; no runtime allocation allowed) ----
__device__ __half g_w[(size_t)EXP * DOUT * DIN];
__device__ __half g_x[(size_t)NTOK * DIN];

// ---------------- PTX helpers ----------------
__device__ __forceinline__ void cpa16(uint32_t dst, const void* src, int bytes) {
    asm volatile("cp.async.cg.shared.global [%0], [%1], 16, %2;\n"
                 :: "r"(dst), "l"(src), "r"(bytes));
}
__device__ __forceinline__ void cp_commit() { asm volatile("cp.async.commit_group;\n"); }

__device__ __forceinline__ void ldm4(uint32_t* r, uint32_t a) {
    asm volatile("ldmatrix.sync.aligned.m8n8.x4.shared.b16 {%0,%1,%2,%3}, [%4];\n"
                 : "=r"(r[0]), "=r"(r[1]), "=r"(r[2]), "=r"(r[3]) : "r"(a));
}
__device__ __forceinline__ void mma16816(float* c, const uint32_t* a, uint32_t b0, uint32_t b1) {
    asm volatile("mma.sync.aligned.m16n8k16.row.col.f32.f16.f16.f32 "
                 "{%0,%1,%2,%3}, {%4,%5,%6,%7}, {%8,%9}, {%0,%1,%2,%3};\n"
                 : "+f"(c[0]), "+f"(c[1]), "+f"(c[2]), "+f"(c[3])
                 : "r"(a[0]), "r"(a[1]), "r"(a[2]), "r"(a[3]), "r"(b0), "r"(b1));
}
__device__ __forceinline__ void red2(float* p, float v0, float v1) {
    asm volatile("red.global.add.v2.f32 [%0], {%1,%2};\n" :: "l"(p), "f"(v0), "f"(v1) : "memory");
}

// ---------------- fused prep: blocks [0,8192) = W_eff; [8192,16384) = x + zero out ----------------
__global__ void __launch_bounds__(256, 5) prep_all_kernel(
    const float* __restrict__ weight, const float* __restrict__ lA,
    const float* __restrict__ lB, const float* __restrict__ x,
    float* __restrict__ out)
{
    const int t = threadIdx.x;

    if (blockIdx.x >= WEFF_BLOCKS) {
        size_t i = ((size_t)(blockIdx.x - WEFF_BLOCKS) * 256 + t) * 4;
        float4 v = *reinterpret_cast<const float4*>(x + i);
        reinterpret_cast<__half2*>(g_x + i)[0] =
            __halves2half2(__float2half_rn(v.x), __float2half_rn(v.y));
        reinterpret_cast<__half2*>(g_x + i)[1] =
            __halves2half2(__float2half_rn(v.z), __float2half_rn(v.w));
        *reinterpret_cast<float4*>(out + i) = make_float4(0.f, 0.f, 0.f, 0.f);
        return;
    }

    __shared__ float Bs[64][16];
    __shared__ __align__(16) float As[16][68];
    const int b = blockIdx.x;
    const int e = b >> 10;
    const int jt = (b >> 5) & 31;
    const int dt = b & 31;
    const int j0 = jt * 64, d0 = dt * 64;
    {
        int jj = t >> 2, q = t & 3;
        float4 v = *reinterpret_cast<const float4*>(lB + ((size_t)e * DOUT + j0 + jj) * 16 + q * 4);
        Bs[jj][q * 4 + 0] = v.x; Bs[jj][q * 4 + 1] = v.y;
        Bs[jj][q * 4 + 2] = v.z; Bs[jj][q * 4 + 3] = v.w;
    }
    {
        int r = t >> 4, dd = (t & 15) * 4;
        float4 v = *reinterpret_cast<const float4*>(lA + ((size_t)e * 16 + r) * DIN + d0 + dd);
        *reinterpret_cast<float4*>(&As[r][dd]) = v;
    }
    __syncthreads();
    const int tj = t >> 4, td = t & 15;

    float dw[4][4];
    #pragma unroll
    for (int a = 0; a < 4; a++)
        #pragma unroll
        for (int q = 0; q < 4; q++) dw[a][q] = 0.f;

    #pragma unroll
    for (int r = 0; r < 16; r++) {
        float4 a4 = *reinterpret_cast<const float4*>(&As[r][td * 4]);
        #pragma unroll
        for (int a = 0; a < 4; a++) {
            float bb = Bs[tj * 4 + a][r];
            dw[a][0] += bb * a4.x;
            dw[a][1] += bb * a4.y;
            dw[a][2] += bb * a4.z;
            dw[a][3] += bb * a4.w;
        }
    }

    size_t base0 = ((size_t)e * DOUT + j0 + tj * 4) * DIN + d0 + td * 4;
    #pragma unroll
    for (int a = 0; a < 4; a++) {
        size_t base = base0 + (size_t)a * DIN;
        float4 w = *reinterpret_cast<const float4*>(weight + base);
        __half h0 = __float2half_rn(w.x + 2.0f * dw[a][0]);
        __half h1 = __float2half_rn(w.y + 2.0f * dw[a][1]);
        __half h2 = __float2half_rn(w.z + 2.0f * dw[a][2]);
        __half h3 = __float2half_rn(w.w + 2.0f * dw[a][3]);
        reinterpret_cast<__half2*>(g_w + base)[0] = __halves2half2(h0, h1);
        reinterpret_cast<__half2*>(g_w + base)[1] = __halves2half2(h2, h3);
    }
}

// ---------------- grouped GEMM (fp16, mma.sync, 128x256 CTA tile, TK=64, 3-stage,
//                  512 thr, 64x32 warp tile, 1 CTA/SM) ----------------
__global__ void __launch_bounds__(512, 1) moe_gemm(
    const int* __restrict__ ssi, const int* __restrict__ eoff,
    const float* __restrict__ gates, float* __restrict__ out)
{
    extern __shared__ __align__(256) char smem[];
    uint32_t sb = (uint32_t)__cvta_generic_to_shared(smem);
    int*   tok_s  = reinterpret_cast<int*>(smem);
    float* gate_s = reinterpret_cast<float*>(smem + TM * 4);
    const uint32_t sbuf = sb + 1024;

    const int n0 = blockIdx.x * TN;   // n fastest -> x rows L2-resident across n
    const int mt = blockIdx.y;

    int expert = -1, m0 = 0, mcnt = 0;
    {
        int prev = 0, acc_t = 0;
        #pragma unroll
        for (int e = 0; e < EXP; e++) {
            int end = eoff[e];
            int cnt = end - prev;
            int tiles = (cnt + TM - 1) / TM;
            if (expert < 0 && mt >= acc_t && mt < acc_t + tiles) {
                expert = e;
                m0 = prev + (mt - acc_t) * TM;
                mcnt = end - m0;
                if (mcnt > TM) mcnt = TM;
            }
            acc_t += tiles;
            prev = end;
        }
    }
    if (expert < 0) return;

    const int tid  = threadIdx.x;
    const int lane = tid & 31;
    const int warp = tid >> 5;
    const int wm   = warp & 1;    // 0..1 : 64-row slice
    const int wn   = warp >> 1;   // 0..7 : 32-col slice

    if (tid < TM) {
        int tok = -1; float g = 0.f;
        if (tid < mcnt) {
            int s = ssi[m0 + tid];
            tok = s / KROUTE;
            int slot = s - tok * KROUTE;
            g = gates[tok * KROUTE + slot];
        }
        tok_s[tid]  = tok;
        gate_s[tid] = g;
    }
    __syncthreads();

    float acc[4][4][4];
    #pragma unroll
    for (int i = 0; i < 4; i++)
        #pragma unroll
        for (int j = 0; j < 4; j++)
            #pragma unroll
            for (int q = 0; q < 4; q++) acc[i][j][q] = 0.f;

    const size_t wbase = (size_t)expert * DOUT * DIN;

    auto load_stage = [&](int buf, int kb) {
        const int k0 = kb * TK;
        const uint32_t s = sbuf + (uint32_t)buf * STGB;
        // A: 1024 chunks of 16B (128 rows x 8)
        #pragma unroll
        for (int it = 0; it < 2; it++) {
            int idx = tid + it * 512;
            int row = idx >> 3, c = idx & 7;
            uint32_t soff = (uint32_t)(row * (LDSS * 2) + c * 16);
            int tok = tok_s[row];
            size_t xoff = (size_t)(tok < 0 ? 0 : tok) * DIN + k0 + c * 8;
            int bytes = (tok < 0) ? 0 : 16;
            cpa16(s + soff, g_x + xoff, bytes);
        }
        // W: 2048 chunks of 16B (256 rows x 8)
        #pragma unroll
        for (int it = 0; it < 4; it++) {
            int idx = tid + it * 512;
            int row = idx >> 3, c = idx & 7;
            uint32_t soff = (uint32_t)(row * (LDSS * 2) + c * 16);
            size_t woff = wbase + (size_t)(n0 + row) * DIN + k0 + c * 8;
            cpa16(s + ATILE + soff, g_w + woff, 16);
        }
        cp_commit();
    };

    load_stage(0, 0);
    load_stage(1, 1);

    int buf = 0;
    for (int kb = 0; kb < KB; kb++) {
        asm volatile("cp.async.wait_group 1;\n");
        __syncthreads();
        if (kb + 2 < KB) {
            int nb = buf + 2; if (nb >= NSTG) nb -= NSTG;
            load_stage(nb, kb + 2);
        } else {
            cp_commit();   // keep group-count invariant
        }

        const uint32_t aX = sbuf + (uint32_t)buf * STGB;
        const uint32_t bW = aX + ATILE;

        #pragma unroll
        for (int ks = 0; ks < 4; ks++) {
            uint32_t ax[4][4], bw[2][4];
            int arow = wm * 64 + (lane & 15);
            int acol = ks * 16 + (lane >> 4) * 8;
            #pragma unroll
            for (int mi = 0; mi < 4; mi++) {
                uint32_t off = (uint32_t)((arow + mi * 16) * LDSS + acol) * 2;
                ldm4(ax[mi], aX + off);
            }
            int brow = wn * 32 + (lane & 7) + ((lane >> 4) << 3);
            int bcol = ks * 16 + ((lane >> 3) & 1) * 8;
            #pragma unroll
            for (int nq = 0; nq < 2; nq++) {
                uint32_t off = (uint32_t)((brow + nq * 16) * LDSS + bcol) * 2;
                ldm4(bw[nq], bW + off);
            }
            #pragma unroll
            for (int ni = 0; ni < 4; ni++) {
                uint32_t b0 = bw[ni >> 1][(ni & 1) * 2 + 0];
                uint32_t b1 = bw[ni >> 1][(ni & 1) * 2 + 1];
                #pragma unroll
                for (int mi = 0; mi < 4; mi++) {
                    mma16816(acc[mi][ni], ax[mi], b0, b1);
                }
            }
        }
        buf = (buf + 1 == NSTG) ? 0 : buf + 1;
    }

    // epilogue: gate + scatter red.add (k=2 routes collide per token)
    const int g = lane >> 2, tg = lane & 3;
    #pragma unroll
    for (int mi = 0; mi < 4; mi++) {
        #pragma unroll
        for (int half = 0; half < 2; half++) {
            int mr = wm * 64 + mi * 16 + g + half * 8;
            int tok = tok_s[mr];
            if (tok < 0) continue;
            float gg = gate_s[mr];
            float* orow = out + (size_t)tok * DOUT + n0 + wn * 32 + tg * 2;
            #pragma unroll
            for (int ni = 0; ni < 4; ni++) {
                red2(orow + ni * 8,
                     acc[mi][ni][half * 2 + 0] * gg,
                     acc[mi][ni][half * 2 + 1] * gg);
            }
        }
    }
}

// ---------------- launch ----------------
extern "C" void kernel_launch(void* const* d_in, const int* in_sizes, int n_in,
                              void* d_out, int out_size) {
    const float* inputs = (const float*)d_in[0];
    const float* weight = (const float*)d_in[1];
    const float* lora_A = (const float*)d_in[2];
    const float* lora_B = (const float*)d_in[3];
    const float* gates  = (const float*)d_in[4];
    const int*   ssi    = (const int*)d_in[6];
    const int*   eoff   = (const int*)d_in[7];
    float* out = (float*)d_out;

    const int SMEM_BYTES = 1024 + NSTG * STGB;   // 1024 + 165888 = 166912
    cudaFuncSetAttribute(moe_gemm, cudaFuncAttributeMaxDynamicSharedMemorySize, SMEM_BYTES);

    prep_all_kernel<<<WEFF_BLOCKS + PREPX_BLOCKS, 256>>>(weight, lora_A, lora_B, inputs, out);

    dim3 grid(DOUT / TN, MTOT / TM + EXP);   // 8 x 72
    moe_gemm<<<grid, 512, SMEM_BYTES>>>(ssi, eoff, gates, out);
}

// round 16
// speedup vs baseline: 1.0791x; 1.0791x over previous
#include <cuda_runtime.h>
#include <cuda_fp16.h>
#include <cstdint>

#define EXP    8
#define DIN    2048
#define DOUT   2048
#define NTOK   4096
#define KROUTE 2
#define MTOT   (NTOK * KROUTE)

#define TM 128
#define TN 128
#define TK 64
#define KB (DIN / TK)             // 32
#define NSTG 3
#define LDSS 72                   // padded smem row stride in fp16 elems (144B)
#define TILEB (TM * LDSS * 2)     // 18432 bytes per tile
#define STGB  (2 * TILEB)         // X, W per stage = 36864

#define WEFF_BLOCKS (EXP * 32 * 32)          // 8192
#define PREPX_BLOCKS ((NTOK * DIN) / 1024)   // 8192

// ---- scratch (device globals; no runtime allocation allowed) ----
__device__ __half g_w[(size_t)EXP * DOUT * DIN];
__device__ __half g_x[(size_t)NTOK * DIN];

// ---------------- PTX helpers ----------------
__device__ __forceinline__ void cpa16(uint32_t dst, const void* src, int bytes) {
    asm volatile("cp.async.cg.shared.global [%0], [%1], 16, %2;\n"
                 :: "r"(dst), "l"(src), "r"(bytes));
}
__device__ __forceinline__ void cp_commit() { asm volatile("cp.async.commit_group;\n"); }

__device__ __forceinline__ void ldm4(uint32_t* r, uint32_t a) {
    asm volatile("ldmatrix.sync.aligned.m8n8.x4.shared.b16 {%0,%1,%2,%3}, [%4];\n"
                 : "=r"(r[0]), "=r"(r[1]), "=r"(r[2]), "=r"(r[3]) : "r"(a));
}
__device__ __forceinline__ void mma16816(float* c, const uint32_t* a, uint32_t b0, uint32_t b1) {
    asm volatile("mma.sync.aligned.m16n8k16.row.col.f32.f16.f16.f32 "
                 "{%0,%1,%2,%3}, {%4,%5,%6,%7}, {%8,%9}, {%0,%1,%2,%3};\n"
                 : "+f"(c[0]), "+f"(c[1]), "+f"(c[2]), "+f"(c[3])
                 : "r"(a[0]), "r"(a[1]), "r"(a[2]), "r"(a[3]), "r"(b0), "r"(b1));
}
__device__ __forceinline__ void red2(float* p, float v0, float v1) {
    asm volatile("red.global.add.v2.f32 [%0], {%1,%2};\n" :: "l"(p), "f"(v0), "f"(v1) : "memory");
}

// ---------------- fused prep: blocks [0,8192) = W_eff; [8192,16384) = x + zero out ----------------
__global__ void __launch_bounds__(256, 5) prep_all_kernel(
    const float* __restrict__ weight, const float* __restrict__ lA,
    const float* __restrict__ lB, const float* __restrict__ x,
    float* __restrict__ out)
{
    const int t = threadIdx.x;

    if (blockIdx.x >= WEFF_BLOCKS) {
        size_t i = ((size_t)(blockIdx.x - WEFF_BLOCKS) * 256 + t) * 4;
        float4 v = *reinterpret_cast<const float4*>(x + i);
        reinterpret_cast<__half2*>(g_x + i)[0] =
            __halves2half2(__float2half_rn(v.x), __float2half_rn(v.y));
        reinterpret_cast<__half2*>(g_x + i)[1] =
            __halves2half2(__float2half_rn(v.z), __float2half_rn(v.w));
        *reinterpret_cast<float4*>(out + i) = make_float4(0.f, 0.f, 0.f, 0.f);
        return;
    }

    __shared__ float Bs[64][16];
    __shared__ __align__(16) float As[16][68];
    const int b = blockIdx.x;
    const int e = b >> 10;
    const int jt = (b >> 5) & 31;
    const int dt = b & 31;
    const int j0 = jt * 64, d0 = dt * 64;
    {
        int jj = t >> 2, q = t & 3;
        float4 v = *reinterpret_cast<const float4*>(lB + ((size_t)e * DOUT + j0 + jj) * 16 + q * 4);
        Bs[jj][q * 4 + 0] = v.x; Bs[jj][q * 4 + 1] = v.y;
        Bs[jj][q * 4 + 2] = v.z; Bs[jj][q * 4 + 3] = v.w;
    }
    {
        int r = t >> 4, dd = (t & 15) * 4;
        float4 v = *reinterpret_cast<const float4*>(lA + ((size_t)e * 16 + r) * DIN + d0 + dd);
        *reinterpret_cast<float4*>(&As[r][dd]) = v;
    }
    __syncthreads();
    const int tj = t >> 4, td = t & 15;

    float dw[4][4];
    #pragma unroll
    for (int a = 0; a < 4; a++)
        #pragma unroll
        for (int q = 0; q < 4; q++) dw[a][q] = 0.f;

    #pragma unroll
    for (int r = 0; r < 16; r++) {
        float4 a4 = *reinterpret_cast<const float4*>(&As[r][td * 4]);
        #pragma unroll
        for (int a = 0; a < 4; a++) {
            float bb = Bs[tj * 4 + a][r];
            dw[a][0] += bb * a4.x;
            dw[a][1] += bb * a4.y;
            dw[a][2] += bb * a4.z;
            dw[a][3] += bb * a4.w;
        }
    }

    size_t base0 = ((size_t)e * DOUT + j0 + tj * 4) * DIN + d0 + td * 4;
    #pragma unroll
    for (int a = 0; a < 4; a++) {
        size_t base = base0 + (size_t)a * DIN;
        float4 w = *reinterpret_cast<const float4*>(weight + base);
        __half h0 = __float2half_rn(w.x + 2.0f * dw[a][0]);
        __half h1 = __float2half_rn(w.y + 2.0f * dw[a][1]);
        __half h2 = __float2half_rn(w.z + 2.0f * dw[a][2]);
        __half h3 = __float2half_rn(w.w + 2.0f * dw[a][3]);
        reinterpret_cast<__half2*>(g_w + base)[0] = __halves2half2(h0, h1);
        reinterpret_cast<__half2*>(g_w + base)[1] = __halves2half2(h2, h3);
    }
}

// ---------------- grouped GEMM (fp16, mma.sync, TK=64, 3-stage, 256 thr, 64x32 warp tile, 2 CTA/SM) ----------------
__global__ void __launch_bounds__(256, 2) moe_gemm(
    const int* __restrict__ ssi, const int* __restrict__ eoff,
    const float* __restrict__ gates, float* __restrict__ out)
{
    extern __shared__ __align__(256) char smem[];
    uint32_t sb = (uint32_t)__cvta_generic_to_shared(smem);
    int*   tok_s  = reinterpret_cast<int*>(smem);
    float* gate_s = reinterpret_cast<float*>(smem + TM * 4);
    const uint32_t sbuf = sb + 1024;

    const int n0 = blockIdx.x * TN;   // n fastest -> x rows L2-resident across n
    const int mt = blockIdx.y;

    int expert = -1, m0 = 0, mcnt = 0;
    {
        int prev = 0, acc_t = 0;
        #pragma unroll
        for (int e = 0; e < EXP; e++) {
            int end = eoff[e];
            int cnt = end - prev;
            int tiles = (cnt + TM - 1) / TM;
            if (expert < 0 && mt >= acc_t && mt < acc_t + tiles) {
                expert = e;
                m0 = prev + (mt - acc_t) * TM;
                mcnt = end - m0;
                if (mcnt > TM) mcnt = TM;
            }
            acc_t += tiles;
            prev = end;
        }
    }
    if (expert < 0) return;

    const int tid  = threadIdx.x;
    const int lane = tid & 31;
    const int warp = tid >> 5;
    const int wm   = warp & 1;    // 0..1 : 64-row slice
    const int wn   = warp >> 1;   // 0..3 : 32-col slice

    if (tid < TM) {
        int tok = -1; float g = 0.f;
        if (tid < mcnt) {
            int s = ssi[m0 + tid];
            tok = s / KROUTE;
            int slot = s - tok * KROUTE;
            g = gates[tok * KROUTE + slot];
        }
        tok_s[tid]  = tok;
        gate_s[tid] = g;
    }
    __syncthreads();

    float acc[4][4][4];
    #pragma unroll
    for (int i = 0; i < 4; i++)
        #pragma unroll
        for (int j = 0; j < 4; j++)
            #pragma unroll
            for (int q = 0; q < 4; q++) acc[i][j][q] = 0.f;

    const size_t wbase = (size_t)expert * DOUT * DIN;

    auto load_stage = [&](int buf, int kb) {
        const int k0 = kb * TK;
        const uint32_t s = sbuf + (uint32_t)buf * STGB;
        #pragma unroll
        for (int it = 0; it < 4; it++) {
            int idx = tid + it * 256;         // 0..1023
            int row = idx >> 3, c = idx & 7;  // 8 chunks of 16B per 128B row
            uint32_t soff = (uint32_t)(row * (LDSS * 2) + c * 16);
            int tok = tok_s[row];
            size_t xoff = (size_t)(tok < 0 ? 0 : tok) * DIN + k0 + c * 8;
            int bytes = (tok < 0) ? 0 : 16;
            cpa16(s + soff, g_x + xoff, bytes);
            size_t woff = wbase + (size_t)(n0 + row) * DIN + k0 + c * 8;
            cpa16(s + TILEB + soff, g_w + woff, 16);
        }
        cp_commit();
    };

    load_stage(0, 0);
    load_stage(1, 1);

    int buf = 0;
    for (int kb = 0; kb < KB; kb++) {
        asm volatile("cp.async.wait_group 1;\n");
        __syncthreads();
        if (kb + 2 < KB) {
            int nb = buf + 2; if (nb >= NSTG) nb -= NSTG;
            load_stage(nb, kb + 2);
        } else {
            cp_commit();   // keep group-count invariant
        }

        const uint32_t aX = sbuf + (uint32_t)buf * STGB;
        const uint32_t bW = aX + TILEB;

        #pragma unroll
        for (int ks = 0; ks < 4; ks++) {
            uint32_t ax[4][4], bw[2][4];
            // B fragments first: first HMMA depends on ax[0]+bw[0]; issuing bw
            // earlier shortens the critical-path wait on the last-needed operand.
            int brow = wn * 32 + (lane & 7) + ((lane >> 4) << 3);
            int bcol = ks * 16 + ((lane >> 3) & 1) * 8;
            #pragma unroll
            for (int nq = 0; nq < 2; nq++) {
                uint32_t off = (uint32_t)((brow + nq * 16) * LDSS + bcol) * 2;
                ldm4(bw[nq], bW + off);
            }
            int arow = wm * 64 + (lane & 15);
            int acol = ks * 16 + (lane >> 4) * 8;
            #pragma unroll
            for (int mi = 0; mi < 4; mi++) {
                uint32_t off = (uint32_t)((arow + mi * 16) * LDSS + acol) * 2;
                ldm4(ax[mi], aX + off);
            }
            #pragma unroll
            for (int ni = 0; ni < 4; ni++) {
                uint32_t b0 = bw[ni >> 1][(ni & 1) * 2 + 0];
                uint32_t b1 = bw[ni >> 1][(ni & 1) * 2 + 1];
                #pragma unroll
                for (int mi = 0; mi < 4; mi++) {
                    mma16816(acc[mi][ni], ax[mi], b0, b1);
                }
            }
        }
        buf = (buf + 1 == NSTG) ? 0 : buf + 1;
    }

    // epilogue: gate + scatter red.add (k=2 routes collide per token)
    const int g = lane >> 2, tg = lane & 3;
    #pragma unroll
    for (int mi = 0; mi < 4; mi++) {
        #pragma unroll
        for (int half = 0; half < 2; half++) {
            int mr = wm * 64 + mi * 16 + g + half * 8;
            int tok = tok_s[mr];
            if (tok < 0) continue;
            float gg = gate_s[mr];
            float* orow = out + (size_t)tok * DOUT + n0 + wn * 32 + tg * 2;
            #pragma unroll
            for (int ni = 0; ni < 4; ni++) {
                red2(orow + ni * 8,
                     acc[mi][ni][half * 2 + 0] * gg,
                     acc[mi][ni][half * 2 + 1] * gg);
            }
        }
    }
}

// ---------------- launch ----------------
extern "C" void kernel_launch(void* const* d_in, const int* in_sizes, int n_in,
                              void* d_out, int out_size) {
    const float* inputs = (const float*)d_in[0];
    const float* weight = (const float*)d_in[1];
    const float* lora_A = (const float*)d_in[2];
    const float* lora_B = (const float*)d_in[3];
    const float* gates  = (const float*)d_in[4];
    const int*   ssi    = (const int*)d_in[6];
    const int*   eoff   = (const int*)d_in[7];
    float* out = (float*)d_out;

    const int SMEM_BYTES = 1024 + NSTG * STGB;   // 1024 + 110592 = 111616
    cudaFuncSetAttribute(moe_gemm, cudaFuncAttributeMaxDynamicSharedMemorySize, SMEM_BYTES);

    prep_all_kernel<<<WEFF_BLOCKS + PREPX_BLOCKS, 256>>>(weight, lora_A, lora_B, inputs, out);

    dim3 grid(DOUT / TN, MTOT / TM + EXP);   // 16 x 72
    moe_gemm<<<grid, 256, SMEM_BYTES>>>(ssi, eoff, gates, out);
}

// round 17
// speedup vs baseline: 1.1035x; 1.0226x over previous
#include <cuda_runtime.h>
#include <cuda_fp16.h>
#include <cstdint>

#define EXP    8
#define DIN    2048
#define DOUT   2048
#define NTOK   4096
#define KROUTE 2
#define MTOT   (NTOK * KROUTE)

#define TM 128
#define TN 128
#define TK 64
#define KB (DIN / TK)             // 32
#define NSTG 3
#define LDSS 72                   // padded smem row stride for X tile (144B)
#define ATILE (TM * LDSS * 2)     // 18432 B (X tile)
#define WTILE 16384               // W tile: 128 rows x 128B, swizzled, contiguous
#define STGB  (ATILE + WTILE)     // 34816 B per stage

#define WEFF_BLOCKS (EXP * 32 * 32)          // 8192
#define PREPX_BLOCKS ((NTOK * DIN) / 1024)   // 8192

// ---- scratch (device globals; no runtime allocation allowed) ----
// W stored as tiled+swizzled blocks: [e][nblk(16)][kblk(32)] x 16384B
__device__ __align__(256) __half g_wt[(size_t)EXP * DOUT * DIN];
__device__ __half g_x[(size_t)NTOK * DIN];

// ---------------- PTX helpers ----------------
__device__ __forceinline__ void cpa16(uint32_t dst, const void* src, int bytes) {
    asm volatile("cp.async.cg.shared.global [%0], [%1], 16, %2;\n"
                 :: "r"(dst), "l"(src), "r"(bytes));
}
__device__ __forceinline__ void cp_commit() { asm volatile("cp.async.commit_group;\n"); }

__device__ __forceinline__ void bulk_ld(uint32_t dst, const void* src, uint32_t bytes, uint32_t mbar) {
    asm volatile("cp.async.bulk.shared::cta.global.mbarrier::complete_tx::bytes [%0], [%1], %2, [%3];\n"
                 :: "r"(dst), "l"(src), "r"(bytes), "r"(mbar) : "memory");
}
__device__ __forceinline__ void mbar_init(uint32_t a, uint32_t cnt) {
    asm volatile("mbarrier.init.shared.b64 [%0], %1;" :: "r"(a), "r"(cnt) : "memory");
}
__device__ __forceinline__ void mbar_expect(uint32_t a, uint32_t bytes) {
    asm volatile("mbarrier.arrive.expect_tx.shared.b64 _, [%0], %1;" :: "r"(a), "r"(bytes) : "memory");
}
__device__ __forceinline__ void mbar_wait(uint32_t a, uint32_t ph) {
    asm volatile(
        "{\n .reg .pred P;\n"
        "W%=:\n mbarrier.try_wait.parity.acquire.cta.shared::cta.b64 P, [%0], %1, 0x989680;\n"
        " @P bra D%=;\n bra W%=;\nD%=:\n}"
        :: "r"(a), "r"(ph) : "memory");
}
__device__ __forceinline__ void ldm4(uint32_t* r, uint32_t a) {
    asm volatile("ldmatrix.sync.aligned.m8n8.x4.shared.b16 {%0,%1,%2,%3}, [%4];\n"
                 : "=r"(r[0]), "=r"(r[1]), "=r"(r[2]), "=r"(r[3]) : "r"(a));
}
__device__ __forceinline__ void mma16816(float* c, const uint32_t* a, uint32_t b0, uint32_t b1) {
    asm volatile("mma.sync.aligned.m16n8k16.row.col.f32.f16.f16.f32 "
                 "{%0,%1,%2,%3}, {%4,%5,%6,%7}, {%8,%9}, {%0,%1,%2,%3};\n"
                 : "+f"(c[0]), "+f"(c[1]), "+f"(c[2]), "+f"(c[3])
                 : "r"(a[0]), "r"(a[1]), "r"(a[2]), "r"(a[3]), "r"(b0), "r"(b1));
}
__device__ __forceinline__ void red2(float* p, float v0, float v1) {
    asm volatile("red.global.add.v2.f32 [%0], {%1,%2};\n" :: "l"(p), "f"(v0), "f"(v1) : "memory");
}

// ---------------- fused prep: blocks [0,8192) = W_eff (tiled/swizzled); rest = x + zero out ----------------
__global__ void __launch_bounds__(256, 5) prep_all_kernel(
    const float* __restrict__ weight, const float* __restrict__ lA,
    const float* __restrict__ lB, const float* __restrict__ x,
    float* __restrict__ out)
{
    const int t = threadIdx.x;

    if (blockIdx.x >= WEFF_BLOCKS) {
        size_t i = ((size_t)(blockIdx.x - WEFF_BLOCKS) * 256 + t) * 4;
        float4 v = *reinterpret_cast<const float4*>(x + i);
        reinterpret_cast<__half2*>(g_x + i)[0] =
            __halves2half2(__float2half_rn(v.x), __float2half_rn(v.y));
        reinterpret_cast<__half2*>(g_x + i)[1] =
            __halves2half2(__float2half_rn(v.z), __float2half_rn(v.w));
        *reinterpret_cast<float4*>(out + i) = make_float4(0.f, 0.f, 0.f, 0.f);
        return;
    }

    __shared__ float Bs[64][16];
    __shared__ __align__(16) float As[16][68];
    const int b = blockIdx.x;
    const int e = b >> 10;
    const int jt = (b >> 5) & 31;
    const int dt = b & 31;
    const int j0 = jt * 64, d0 = dt * 64;
    {
        int jj = t >> 2, q = t & 3;
        float4 v = *reinterpret_cast<const float4*>(lB + ((size_t)e * DOUT + j0 + jj) * 16 + q * 4);
        Bs[jj][q * 4 + 0] = v.x; Bs[jj][q * 4 + 1] = v.y;
        Bs[jj][q * 4 + 2] = v.z; Bs[jj][q * 4 + 3] = v.w;
    }
    {
        int r = t >> 4, dd = (t & 15) * 4;
        float4 v = *reinterpret_cast<const float4*>(lA + ((size_t)e * 16 + r) * DIN + d0 + dd);
        *reinterpret_cast<float4*>(&As[r][dd]) = v;
    }
    __syncthreads();
    const int tj = t >> 4, td = t & 15;

    float dw[4][4];
    #pragma unroll
    for (int a = 0; a < 4; a++)
        #pragma unroll
        for (int q = 0; q < 4; q++) dw[a][q] = 0.f;

    #pragma unroll
    for (int r = 0; r < 16; r++) {
        float4 a4 = *reinterpret_cast<const float4*>(&As[r][td * 4]);
        #pragma unroll
        for (int a = 0; a < 4; a++) {
            float bb = Bs[tj * 4 + a][r];
            dw[a][0] += bb * a4.x;
            dw[a][1] += bb * a4.y;
            dw[a][2] += bb * a4.z;
            dw[a][3] += bb * a4.w;
        }
    }

    // write to tiled+swizzled layout: block (e, nblk=j>>7, kblk=d>>6), 16KB each,
    // inner: row=j&127 (128B), chunk c=(d&63)>>3 stored at c^(row&7)
    const int nblk = jt >> 1;
    const int rowbase = (jt & 1) * 64 + tj * 4;
    const size_t blockbase = (((size_t)e * 16 + nblk) * 32 + dt) * 16384;  // bytes
    const int c = td >> 1;
    const int posb = (td & 1) * 8;
    char* gw = reinterpret_cast<char*>(g_wt);

    #pragma unroll
    for (int a = 0; a < 4; a++) {
        int j = j0 + tj * 4 + a;
        size_t wbase = ((size_t)e * DOUT + j) * DIN + d0 + td * 4;
        float4 w = *reinterpret_cast<const float4*>(weight + wbase);
        __half2 h01 = __halves2half2(__float2half_rn(w.x + 2.0f * dw[a][0]),
                                     __float2half_rn(w.y + 2.0f * dw[a][1]));
        __half2 h23 = __halves2half2(__float2half_rn(w.z + 2.0f * dw[a][2]),
                                     __float2half_rn(w.w + 2.0f * dw[a][3]));
        int row = rowbase + a;
        size_t byteoff = blockbase + (size_t)row * 128 + ((c ^ (row & 7)) * 16) + posb;
        *reinterpret_cast<__half2*>(gw + byteoff)     = h01;
        *reinterpret_cast<__half2*>(gw + byteoff + 4) = h23;
    }
}

// ---------------- grouped GEMM (fp16, mma.sync, TK=64, 3-stage, 256 thr, 64x32 warp tile,
//                  2 CTA/SM, W via cp.async.bulk + swizzled tiles) ----------------
__global__ void __launch_bounds__(256, 2) moe_gemm(
    const int* __restrict__ ssi, const int* __restrict__ eoff,
    const float* __restrict__ gates, float* __restrict__ out)
{
    extern __shared__ __align__(256) char smem[];
    uint32_t sb = (uint32_t)__cvta_generic_to_shared(smem);
    const uint32_t mbar0 = sb;                 // 3 mbarriers, 8B each
    int*   tok_s  = reinterpret_cast<int*>(smem + 64);
    float* gate_s = reinterpret_cast<float*>(smem + 64 + 512);
    const uint32_t sbuf = sb + 2048;

    const int n0 = blockIdx.x * TN;   // n fastest -> x rows L2-resident across n
    const int mt = blockIdx.y;

    int expert = -1, m0 = 0, mcnt = 0;
    {
        int prev = 0, acc_t = 0;
        #pragma unroll
        for (int e = 0; e < EXP; e++) {
            int end = eoff[e];
            int cnt = end - prev;
            int tiles = (cnt + TM - 1) / TM;
            if (expert < 0 && mt >= acc_t && mt < acc_t + tiles) {
                expert = e;
                m0 = prev + (mt - acc_t) * TM;
                mcnt = end - m0;
                if (mcnt > TM) mcnt = TM;
            }
            acc_t += tiles;
            prev = end;
        }
    }
    if (expert < 0) return;

    const int tid  = threadIdx.x;
    const int lane = tid & 31;
    const int warp = tid >> 5;
    const int wm   = warp & 1;    // 0..1 : 64-row slice
    const int wn   = warp >> 1;   // 0..3 : 32-col slice

    if (tid < TM) {
        int tok = -1; float g = 0.f;
        if (tid < mcnt) {
            int s = ssi[m0 + tid];
            tok = s / KROUTE;
            int slot = s - tok * KROUTE;
            g = gates[tok * KROUTE + slot];
        }
        tok_s[tid]  = tok;
        gate_s[tid] = g;
    }
    if (tid == 0) {
        mbar_init(mbar0 + 0, 1);
        mbar_init(mbar0 + 8, 1);
        mbar_init(mbar0 + 16, 1);
    }
    __syncthreads();

    float acc[4][4][4];
    #pragma unroll
    for (int i = 0; i < 4; i++)
        #pragma unroll
        for (int j = 0; j < 4; j++)
            #pragma unroll
            for (int q = 0; q < 4; q++) acc[i][j][q] = 0.f;

    // W tile blocks for this (expert, nblk): 32 consecutive 16KB blocks over kblk
    const char* wsrc_base = reinterpret_cast<const char*>(g_wt)
                          + (((size_t)expert * 16 + blockIdx.x) * 32) * 16384;

    auto load_stage = [&](int buf, int kb) {
        const int k0 = kb * TK;
        const uint32_t s = sbuf + (uint32_t)buf * STGB;
        // X: 1024 chunks of 16B, gathered per token row
        #pragma unroll
        for (int it = 0; it < 4; it++) {
            int idx = tid + it * 256;
            int row = idx >> 3, c = idx & 7;
            uint32_t soff = (uint32_t)(row * (LDSS * 2) + c * 16);
            int tok = tok_s[row];
            size_t xoff = (size_t)(tok < 0 ? 0 : tok) * DIN + k0 + c * 8;
            int bytes = (tok < 0) ? 0 : 16;
            cpa16(s + soff, g_x + xoff, bytes);
        }
        cp_commit();
        // W: one bulk DMA of the pre-swizzled 16KB block
        if (tid == 0) {
            uint32_t mb = mbar0 + (uint32_t)((kb % 3) * 8);
            mbar_expect(mb, WTILE);
            bulk_ld(s + ATILE, wsrc_base + (size_t)kb * 16384, WTILE, mb);
        }
    };

    load_stage(0, 0);
    load_stage(1, 1);

    unsigned ph[3] = {0, 0, 0};
    int buf = 0;
    for (int kb = 0; kb < KB; kb++) {
        asm volatile("cp.async.wait_group 1;\n");
        int ms = kb % 3;
        mbar_wait(mbar0 + (uint32_t)(ms * 8), ph[ms]);
        ph[ms] ^= 1;
        __syncthreads();
        if (kb + 2 < KB) {
            int nb = buf + 2; if (nb >= NSTG) nb -= NSTG;
            load_stage(nb, kb + 2);
        } else {
            cp_commit();   // keep group-count invariant
        }

        const uint32_t aX = sbuf + (uint32_t)buf * STGB;
        const uint32_t bW = aX + ATILE;

        #pragma unroll
        for (int ks = 0; ks < 4; ks++) {
            uint32_t ax[4][4], bw[2][4];
            // B fragments (swizzled tile: chunk = (ks*2 + hi) ^ (row & 7))
            int browBase = wn * 32 + (lane & 7) + ((lane >> 4) << 3);
            int cchunk = ks * 2 + ((lane >> 3) & 1);
            #pragma unroll
            for (int nq = 0; nq < 2; nq++) {
                int row = browBase + nq * 16;
                uint32_t off = (uint32_t)(row * 128 + ((cchunk ^ (row & 7)) << 4));
                ldm4(bw[nq], bW + off);
            }
            int arow = wm * 64 + (lane & 15);
            int acol = ks * 16 + (lane >> 4) * 8;
            #pragma unroll
            for (int mi = 0; mi < 4; mi++) {
                uint32_t off = (uint32_t)((arow + mi * 16) * LDSS + acol) * 2;
                ldm4(ax[mi], aX + off);
            }
            #pragma unroll
            for (int ni = 0; ni < 4; ni++) {
                uint32_t b0 = bw[ni >> 1][(ni & 1) * 2 + 0];
                uint32_t b1 = bw[ni >> 1][(ni & 1) * 2 + 1];
                #pragma unroll
                for (int mi = 0; mi < 4; mi++) {
                    mma16816(acc[mi][ni], ax[mi], b0, b1);
                }
            }
        }
        buf = (buf + 1 == NSTG) ? 0 : buf + 1;
    }

    // epilogue: gate + scatter red.add (k=2 routes collide per token)
    const int g = lane >> 2, tg = lane & 3;
    #pragma unroll
    for (int mi = 0; mi < 4; mi++) {
        #pragma unroll
        for (int half = 0; half < 2; half++) {
            int mr = wm * 64 + mi * 16 + g + half * 8;
            int tok = tok_s[mr];
            if (tok < 0) continue;
            float gg = gate_s[mr];
            float* orow = out + (size_t)tok * DOUT + n0 + wn * 32 + tg * 2;
            #pragma unroll
            for (int ni = 0; ni < 4; ni++) {
                red2(orow + ni * 8,
                     acc[mi][ni][half * 2 + 0] * gg,
                     acc[mi][ni][half * 2 + 1] * gg);
            }
        }
    }
}

// ---------------- launch ----------------
extern "C" void kernel_launch(void* const* d_in, const int* in_sizes, int n_in,
                              void* d_out, int out_size) {
    const float* inputs = (const float*)d_in[0];
    const float* weight = (const float*)d_in[1];
    const float* lora_A = (const float*)d_in[2];
    const float* lora_B = (const float*)d_in[3];
    const float* gates  = (const float*)d_in[4];
    const int*   ssi    = (const int*)d_in[6];
    const int*   eoff   = (const int*)d_in[7];
    float* out = (float*)d_out;

    const int SMEM_BYTES = 2048 + NSTG * STGB;   // 2048 + 104448 = 106496
    cudaFuncSetAttribute(moe_gemm, cudaFuncAttributeMaxDynamicSharedMemorySize, SMEM_BYTES);

    prep_all_kernel<<<WEFF_BLOCKS + PREPX_BLOCKS, 256>>>(weight, lora_A, lora_B, inputs, out);

    dim3 grid(DOUT / TN, MTOT / TM + EXP);   // 16 x 72
    moe_gemm<<<grid, 256, SMEM_BYTES>>>(ssi, eoff, gates, out);
}